// round 16
// baseline (speedup 1.0000x reference)
#include <cuda_runtime.h>
#include <cuda_fp16.h>
#include <cstdint>

#define DDIM 768
#define NQ   4096
#define KC   65536
#define BM   128
#define BN   128
#define BK   64              // k elems per stage (128B fp16 rows)
#define NSTAGE (DDIM / BK)   // 12
#define CAP  2048
#define MARGIN 2.0e-4f       // collection margin (vs running min)
#define FILTER 1.45e-4f      // finalize filter (vs converged min)

// B stored as e * 65536 in fp16; dot' = dot * 65536
static constexpr float MINUS2INV = -2.0f / 65536.0f;

// ---------------------------------------------------------------------------
// Device scratch (static — no allocations allowed)
// ---------------------------------------------------------------------------
__device__ float g_zsq[NQ];
__device__ float g_esq[KC];
__device__ __half g_Ah[(size_t)NQ * DDIM];    // 6 MB
__device__ __half g_Bh[(size_t)KC * DDIM];    // 100 MB
__device__ unsigned int g_rowmin[NQ];         // ordered-uint encoded float
__device__ int g_cnt[NQ];
__device__ unsigned long long g_cand[(size_t)NQ * CAP];  // (score|idx)
__device__ int g_code[NQ];
__device__ double g_loss;
__device__ int g_done;

// ---------------------------------------------------------------------------
// Helpers
// ---------------------------------------------------------------------------
__device__ __forceinline__ uint32_t smem_u32(const void* p) {
    uint32_t a;
    asm("{ .reg .u64 t; cvta.to.shared.u64 t, %1; cvt.u32.u64 %0, t; }"
        : "=r"(a) : "l"(p));
    return a;
}
#define SW128(off) ((off) ^ (((off) >> 3) & 0x70))
#define CP16(dst, src) \
    asm volatile("cp.async.cg.shared.global [%0], [%1], 16;" :: "r"(dst), "l"(src))
#define CP_COMMIT() asm volatile("cp.async.commit_group;" ::: "memory")
#define CP_WAIT(n)  asm volatile("cp.async.wait_group %0;" :: "n"(n) : "memory")

__device__ __forceinline__ void ldm_x4(uint32_t& r0, uint32_t& r1, uint32_t& r2,
                                       uint32_t& r3, uint32_t addr) {
    asm volatile("ldmatrix.sync.aligned.m8n8.x4.shared.b16 {%0,%1,%2,%3}, [%4];"
                 : "=r"(r0), "=r"(r1), "=r"(r2), "=r"(r3) : "r"(addr));
}
// fp16 HMMA with fp16 accumulators (2 packed half2 regs)
__device__ __forceinline__ void mma_f16acc(uint32_t* d, const uint32_t* a,
                                           uint32_t b0, uint32_t b1) {
    asm volatile(
        "mma.sync.aligned.m16n8k16.row.col.f16.f16.f16.f16 "
        "{%0,%1}, {%2,%3,%4,%5}, {%6,%7}, {%0,%1};"
        : "+r"(d[0]), "+r"(d[1])
        : "r"(a[0]), "r"(a[1]), "r"(a[2]), "r"(a[3]), "r"(b0), "r"(b1));
}

// float <-> ordered uint (atomicMin over signed floats)
__device__ __forceinline__ unsigned fenc(float f) {
    unsigned u = __float_as_uint(f);
    return (u & 0x80000000u) ? ~u : (u | 0x80000000u);
}
__device__ __forceinline__ float fdec(unsigned u) {
    return (u & 0x80000000u) ? __uint_as_float(u & 0x7FFFFFFFu)
                             : __uint_as_float(~u);
}

// ---------------------------------------------------------------------------
// Fused prep (R12 verbatim): init + A + B, coalesced, bit-exact seq norm.
// ---------------------------------------------------------------------------
#define PR 64   // rows per block
#define NA_BLK (NQ / PR)   // 64 A-blocks

__global__ void __launch_bounds__(256) prep_kernel(const float* __restrict__ Ain,
                                                   const float* __restrict__ Bin) {
    __shared__ float tile[PR][65];
    const int tid = threadIdx.x;
    const int b = blockIdx.x;

    const float* X;
    __half* outh;
    float* outn;
    float scale;
    int r0;
    if (b < NA_BLK) {
        X = Ain; outh = g_Ah; outn = g_zsq; scale = 1.0f; r0 = b * PR;
        if (tid < PR) { g_rowmin[r0 + tid] = 0xFFFFFFFFu; g_cnt[r0 + tid] = 0; }
        if (b == 0 && tid == 0) { g_loss = 0.0; g_done = 0; }
    } else {
        X = Bin; outh = g_Bh; outn = g_esq; scale = 65536.0f;
        r0 = (b - NA_BLK) * PR;
    }

    const int rr = tid >> 4;          // 0..15 (+j*16)
    const int c4 = tid & 15;          // float4 index within 64-col chunk

    float4 v[2][4];
    auto ldchunk = [&](int buf, int c) {
#pragma unroll
        for (int j = 0; j < 4; j++)
            v[buf][j] = __ldg(reinterpret_cast<const float4*>(
                X + (size_t)(r0 + rr + j * 16) * DDIM + c + c4 * 4));
    };

    ldchunk(0, 0);
    float s = 0.f;
    int cc = 0;
    for (int c = 0; c < DDIM; c += 64) {
#pragma unroll
        for (int j = 0; j < 4; j++) {
            float4 t = v[cc][j];
            int row = rr + j * 16;
            tile[row][c4 * 4 + 0] = t.x;
            tile[row][c4 * 4 + 1] = t.y;
            tile[row][c4 * 4 + 2] = t.z;
            tile[row][c4 * 4 + 3] = t.w;
            __half2 h0 = __floats2half2_rn(t.x * scale, t.y * scale);
            __half2 h1 = __floats2half2_rn(t.z * scale, t.w * scale);
            uint2 pk;
            pk.x = *reinterpret_cast<unsigned*>(&h0);
            pk.y = *reinterpret_cast<unsigned*>(&h1);
            *reinterpret_cast<uint2*>(outh + (size_t)(r0 + row) * DDIM + c + c4 * 4) = pk;
        }
        if (c + 64 < DDIM) ldchunk(cc ^ 1, c + 64);   // overlap with accumulate
        __syncthreads();
        if (tid < PR) {
#pragma unroll 8
            for (int k = 0; k < 64; k++) {            // bit-exact sequential order
                float t = tile[tid][k];
                s = __fadd_rn(s, __fmul_rn(t, t));
            }
        }
        __syncthreads();
        cc ^= 1;
    }
    if (tid < PR) outn[r0 + tid] = s;
}

// ---------------------------------------------------------------------------
// Pass 1: fp16 HMMA GEMM, 128x128 tile, 3 CTAs/SM (occupancy experiment).
// 8 warps in 2x4; each warp computes 64x32.
// ---------------------------------------------------------------------------
__global__ void __launch_bounds__(256, 3) pass1_kernel() {
    extern __shared__ char smem[];
    const uint32_t sb = smem_u32(smem);
    const uint32_t A_S[2] = {sb, sb + 16384};                 // 128 rows x 128B
    const uint32_t B_S[2] = {sb + 32768, sb + 32768 + 16384}; // 128 rows x 128B

    const int tid = threadIdx.x;
    const int wid = tid >> 5;
    const int lane = tid & 31;
    const int warp_m = wid >> 2;       // 0..1  (64 rows each)
    const int warp_n = wid & 3;        // 0..3  (32 cols each)
    const int bm = blockIdx.x * BM;
    const int bn = blockIdx.y * BN;

    uint32_t acc[4][4][2];             // half2-packed fp16 accumulators
#pragma unroll
    for (int i = 0; i < 4; i++)
#pragma unroll
        for (int j = 0; j < 4; j++) { acc[i][j][0] = 0u; acc[i][j][1] = 0u; }

    // hoisted fill addressing: 32-bit byte offsets; stage advance = +128B
    const char* Abase = reinterpret_cast<const char*>(g_Ah) +
                        (uint32_t)((bm + (tid >> 3)) * (DDIM * 2) + (tid & 7) * 16);
    const char* Bbase = reinterpret_cast<const char*>(g_Bh) +
                        (uint32_t)((bn + (tid >> 3)) * (DDIM * 2) + (tid & 7) * 16);
    const uint32_t dstsw = SW128((uint32_t)((tid >> 3) * 128 + (tid & 7) * 16));

    auto fill = [&](int stg, int s) {
        const char* ap = Abase + s * 128;
        const char* bp = Bbase + s * 128;
        const uint32_t da = A_S[stg] + dstsw;
        const uint32_t db = B_S[stg] + dstsw;
#pragma unroll
        for (int i = 0; i < 4; i++)
            CP16(da + i * 4096, ap + i * (32 * DDIM * 2));
#pragma unroll
        for (int i = 0; i < 4; i++)
            CP16(db + i * 4096, bp + i * (32 * DDIM * 2));
        CP_COMMIT();
    };

    fill(0, 0);
    fill(1, 1);

    const int a_r = warp_m * 64 + (lane & 7) + ((lane & 8) ? 8 : 0);  // + mi*16
    const int b_r = warp_n * 32 + (lane & 7) + ((lane & 8) ? 8 : 0);  // + bj*16
    const int chk = (lane >> 4) & 1;

    for (int s = 0; s < NSTAGE; s++) {
        if (s < NSTAGE - 1) { CP_WAIT(1); } else { CP_WAIT(0); }
        __syncthreads();
        const uint32_t Ab = A_S[s & 1], Bb = B_S[s & 1];
#pragma unroll
        for (int kk = 0; kk < 4; kk++) {
            const int ch = chk + kk * 2;
            uint32_t a[4][4];
#pragma unroll
            for (int mi = 0; mi < 4; mi++) {
                int r = a_r + mi * 16;
                ldm_x4(a[mi][0], a[mi][1], a[mi][2], a[mi][3],
                       Ab + (uint32_t)(r * 128 + ((ch * 16) ^ ((r & 7) << 4))));
            }
            uint32_t bf[2][4];
#pragma unroll
            for (int bj = 0; bj < 2; bj++) {
                int r = b_r + bj * 16;
                ldm_x4(bf[bj][0], bf[bj][1], bf[bj][2], bf[bj][3],
                       Bb + (uint32_t)(r * 128 + ((ch * 16) ^ ((r & 7) << 4))));
            }
#pragma unroll
            for (int mi = 0; mi < 4; mi++)
#pragma unroll
                for (int nj = 0; nj < 4; nj++)
                    mma_f16acc(acc[mi][nj], a[mi], bf[nj >> 1][nj & 1],
                               bf[nj >> 1][2 + (nj & 1)]);
        }
        __syncthreads();
        if (s + 2 < NSTAGE) fill(s & 1, s + 2);
    }

    // ---- epilogue: scores, running row-min, packed candidate collection ----
#pragma unroll
    for (int mi = 0; mi < 4; mi++) {
#pragma unroll
        for (int half = 0; half < 2; half++) {
            const int row = bm + warp_m * 64 + mi * 16 + (lane >> 2) + half * 8;
            float rmin = 3.4e38f;
            float sc[4][2];
#pragma unroll
            for (int nj = 0; nj < 4; nj++) {
                float2 d2 = __half22float2(
                    *reinterpret_cast<__half2*>(&acc[mi][nj][half]));
#pragma unroll
                for (int t = 0; t < 2; t++) {
                    int c = bn + warp_n * 32 + nj * 8 + (lane & 3) * 2 + t;
                    float dotp = t == 0 ? d2.x : d2.y;
                    float v = __fmaf_rn(MINUS2INV, dotp, g_esq[c]);
                    sc[nj][t] = v;
                    rmin = fminf(rmin, v);
                }
            }
            rmin = fminf(rmin, __shfl_xor_sync(0xFFFFFFFFu, rmin, 1));
            rmin = fminf(rmin, __shfl_xor_sync(0xFFFFFFFFu, rmin, 2));
            unsigned enc = fenc(rmin);
            unsigned old = 0xFFFFFFFFu;
            if ((lane & 3) == 0) old = atomicMin(&g_rowmin[row], enc);
            old = __shfl_sync(0xFFFFFFFFu, old, lane & ~3);
            float T = fdec(old < enc ? old : enc) + MARGIN;
#pragma unroll
            for (int nj = 0; nj < 4; nj++)
#pragma unroll
                for (int t = 0; t < 2; t++) {
                    if (sc[nj][t] <= T) {
                        int c = bn + warp_n * 32 + nj * 8 + (lane & 3) * 2 + t;
                        int pos = atomicAdd(&g_cnt[row], 1);
                        if (pos < CAP)
                            g_cand[(size_t)row * CAP + pos] =
                                ((unsigned long long)fenc(sc[nj][t]) << 32) |
                                (unsigned long long)(unsigned)c;
                    }
                }
        }
    }
}

// ---------------------------------------------------------------------------
// Rerank: one WARP per row (R15 verbatim).
// ---------------------------------------------------------------------------
__global__ void __launch_bounds__(256) rerank_kernel(const float* __restrict__ A,
                                                     const float* __restrict__ B) {
    const int n = blockIdx.x * 8 + (threadIdx.x >> 5);
    const int lane = threadIdx.x & 31;

    const float zq = g_zsq[n];
    const float thr = fdec(g_rowmin[n]) + FILTER;
    const float* z = A + (size_t)n * DDIM;
    int cnt = g_cnt[n];
    if (cnt > CAP) cnt = CAP;

    unsigned long long best = ~0ULL;
    for (int i = lane; i < cnt; i += 32) {
        unsigned long long key = g_cand[(size_t)n * CAP + i];
        float sc = fdec((unsigned)(key >> 32));
        if (sc > thr) continue;
        int c = (int)(key & 0xFFFFFFFFULL);
        const float4* e4 = reinterpret_cast<const float4*>(B + (size_t)c * DDIM);
        const float4* z4 = reinterpret_cast<const float4*>(z);
        float dot = 0.f;
#pragma unroll 4
        for (int k = 0; k < DDIM / 4; k++) {
            float4 ev = __ldg(&e4[k]);
            float4 zv = __ldg(&z4[k]);
            dot = __fmaf_rn(zv.x, ev.x, dot);
            dot = __fmaf_rn(zv.y, ev.y, dot);
            dot = __fmaf_rn(zv.z, ev.z, dot);
            dot = __fmaf_rn(zv.w, ev.w, dot);
        }
        float anchor = __fadd_rn(zq, g_esq[c]);               // fl(z2 + e2)
        float dist = __fsub_rn(anchor, __fadd_rn(dot, dot));  // fl(a - 2*dot)
        unsigned long long k2 =
            ((unsigned long long)__float_as_uint(dist) << 32) |
            (unsigned long long)(unsigned)c;
        best = k2 < best ? k2 : best;
    }
#pragma unroll
    for (int o = 16; o > 0; o >>= 1) {
        unsigned long long other = __shfl_xor_sync(0xFFFFFFFFu, best, o);
        best = other < best ? other : best;
    }
    if (lane == 0) g_code[n] = (int)(best & 0xFFFFFFFFULL);
}

// ---------------------------------------------------------------------------
// STE + loss (R15 verbatim): block per row, float4 streams, last-block loss.
// ---------------------------------------------------------------------------
__global__ void __launch_bounds__(256) ste_kernel(const float* __restrict__ A,
                                                  const float* __restrict__ B,
                                                  float* __restrict__ out_codes,
                                                  float* __restrict__ out_q,
                                                  float* __restrict__ out_loss,
                                                  double inv_nd) {
    const int n = blockIdx.x;
    const int tid = threadIdx.x;
    const int code = g_code[n];
    if (tid == 0) out_codes[n] = (float)code;

    const float4* z4 = reinterpret_cast<const float4*>(A + (size_t)n * DDIM);
    const float4* q4 = reinterpret_cast<const float4*>(B + (size_t)code * DDIM);
    float4* o4 = reinterpret_cast<float4*>(out_q + (size_t)n * DDIM);

    float ls = 0.f;
    if (tid < DDIM / 4) {                      // 192 active threads
        float4 zv = __ldg(&z4[tid]);
        float4 qv = __ldg(&q4[tid]);
        float4 ov;
        ov.x = __fadd_rn(zv.x, __fsub_rn(qv.x, zv.x));
        ov.y = __fadd_rn(zv.y, __fsub_rn(qv.y, zv.y));
        ov.z = __fadd_rn(zv.z, __fsub_rn(qv.z, zv.z));
        ov.w = __fadd_rn(zv.w, __fsub_rn(qv.w, zv.w));
        o4[tid] = ov;
        float dx = zv.x - qv.x, dy = zv.y - qv.y;
        float dz = zv.z - qv.z, dw = zv.w - qv.w;
        ls = __fmaf_rn(dx, dx, __fmaf_rn(dy, dy,
             __fmaf_rn(dz, dz, __fmul_rn(dw, dw))));
    }
#pragma unroll
    for (int o = 16; o > 0; o >>= 1) ls += __shfl_xor_sync(0xFFFFFFFFu, ls, o);
    __shared__ float wsum[8];
    int w = tid >> 5;
    if ((tid & 31) == 0) wsum[w] = ls;
    __syncthreads();
    if (tid == 0) {
        float s = 0.f;
        for (int k = 0; k < 8; k++) s += wsum[k];
        atomicAdd(&g_loss, (double)s);
        __threadfence();
        int d = atomicAdd(&g_done, 1);
        if (d == (int)gridDim.x - 1) {
            __threadfence();
            out_loss[0] = (float)(g_loss * inv_nd * 1.25);
        }
    }
}

// ---------------------------------------------------------------------------
extern "C" void kernel_launch(void* const* d_in, const int* in_sizes, int n_in,
                              void* d_out, int out_size) {
    const float* A = (const float*)d_in[0];  // embeddings (4096 x 768)
    const float* B = (const float*)d_in[1];  // codebook  (65536 x 768)
    const int N = in_sizes[0] / DDIM;
    const int K = in_sizes[1] / DDIM;

    float* out = (float*)d_out;
    float* out_codes = out;
    float* out_q = out + N;
    float* out_loss = out + N + (size_t)N * DDIM;

    static const int SMEM_BYTES = 4 * 16384;  // 64 KB
    cudaFuncSetAttribute(pass1_kernel, cudaFuncAttributeMaxDynamicSharedMemorySize,
                         SMEM_BYTES);

    // fused prep: init + A + B in one launch
    prep_kernel<<<(N + K) / PR, 256>>>(A, B);

    dim3 grid(N / BM, K / BN);   // (32, 512) — m fastest for B-strip L2 reuse
    pass1_kernel<<<grid, 256, SMEM_BYTES>>>();

    rerank_kernel<<<N / 8, 256>>>(A, B);
    ste_kernel<<<N, 256>>>(A, B, out_codes, out_q, out_loss,
                           1.0 / ((double)N * (double)DDIM));
}

// round 17
// speedup vs baseline: 1.0399x; 1.0399x over previous
#include <cuda_runtime.h>
#include <cuda_fp16.h>
#include <cstdint>

#define DDIM 768
#define NQ   4096
#define KC   65536
#define BM   128
#define BN   256
#define BK   64              // k elems per stage (128B fp16 rows)
#define NSTAGE (DDIM / BK)   // 12
#define CAP  2048
#define MARGIN 2.0e-4f       // collection margin (vs running min)
#define FILTER 1.45e-4f      // finalize filter (vs converged min)

// B stored as e * 65536 in fp16; dot' = dot * 65536
static constexpr float MINUS2INV = -2.0f / 65536.0f;

// ---------------------------------------------------------------------------
// Device scratch (static — no allocations allowed)
// ---------------------------------------------------------------------------
__device__ float g_zsq[NQ];
__device__ float g_esq[KC];
__device__ __half g_Ah[(size_t)NQ * DDIM];    // 6 MB
__device__ __half g_Bh[(size_t)KC * DDIM];    // 100 MB
__device__ unsigned int g_rowmin[NQ];         // ordered-uint encoded float
__device__ int g_cnt[NQ];
__device__ unsigned long long g_cand[(size_t)NQ * CAP];  // (score|idx)
__device__ int g_code[NQ];
__device__ double g_loss;
__device__ int g_done;

// ---------------------------------------------------------------------------
// Helpers
// ---------------------------------------------------------------------------
__device__ __forceinline__ uint32_t smem_u32(const void* p) {
    uint32_t a;
    asm("{ .reg .u64 t; cvta.to.shared.u64 t, %1; cvt.u32.u64 %0, t; }"
        : "=r"(a) : "l"(p));
    return a;
}
#define SW128(off) ((off) ^ (((off) >> 3) & 0x70))
#define CP16(dst, src) \
    asm volatile("cp.async.cg.shared.global [%0], [%1], 16;" :: "r"(dst), "l"(src))
#define CP_COMMIT() asm volatile("cp.async.commit_group;" ::: "memory")
#define CP_WAIT(n)  asm volatile("cp.async.wait_group %0;" :: "n"(n) : "memory")

__device__ __forceinline__ void ldm_x4(uint32_t& r0, uint32_t& r1, uint32_t& r2,
                                       uint32_t& r3, uint32_t addr) {
    asm volatile("ldmatrix.sync.aligned.m8n8.x4.shared.b16 {%0,%1,%2,%3}, [%4];"
                 : "=r"(r0), "=r"(r1), "=r"(r2), "=r"(r3) : "r"(addr));
}
// fp16 HMMA with fp16 accumulators (2 packed half2 regs)
__device__ __forceinline__ void mma_f16acc(uint32_t* d, const uint32_t* a,
                                           uint32_t b0, uint32_t b1) {
    asm volatile(
        "mma.sync.aligned.m16n8k16.row.col.f16.f16.f16.f16 "
        "{%0,%1}, {%2,%3,%4,%5}, {%6,%7}, {%0,%1};"
        : "+r"(d[0]), "+r"(d[1])
        : "r"(a[0]), "r"(a[1]), "r"(a[2]), "r"(a[3]), "r"(b0), "r"(b1));
}

// float <-> ordered uint (atomicMin over signed floats)
__device__ __forceinline__ unsigned fenc(float f) {
    unsigned u = __float_as_uint(f);
    return (u & 0x80000000u) ? ~u : (u | 0x80000000u);
}
__device__ __forceinline__ float fdec(unsigned u) {
    return (u & 0x80000000u) ? __uint_as_float(u & 0x7FFFFFFFu)
                             : __uint_as_float(~u);
}

// ---------------------------------------------------------------------------
// Prep v3: 256 rows/block (one row per thread for the norm chain).
// cp.async double-buffered fp32 smem tile; all 256 threads accumulate in
// parallel; cooperative coalesced fp16 convert. Bit-exact sequential order:
// per row one accumulator, chunk-ascending, k-ascending, fl(mul)+fl(add).
// ---------------------------------------------------------------------------
#define PROWS 256
#define PSTRIDE 68            // floats; keeps 16B cp.async alignment
#define NA_BLK (NQ / PROWS)   // 16 A-blocks
#define PREP_SMEM (2 * PROWS * PSTRIDE * 4)   // 139264 B

__global__ void __launch_bounds__(256) prep_kernel(const float* __restrict__ Ain,
                                                   const float* __restrict__ Bin) {
    extern __shared__ float ptile[];   // [2][PROWS][PSTRIDE]
    const int tid = threadIdx.x;
    const int b = blockIdx.x;

    const float* X;
    __half* outh;
    float* outn;
    float scale;
    int r0;
    if (b < NA_BLK) {
        X = Ain; outh = g_Ah; outn = g_zsq; scale = 1.0f; r0 = b * PROWS;
        g_rowmin[r0 + tid] = 0xFFFFFFFFu;
        g_cnt[r0 + tid] = 0;
        if (b == 0 && tid == 0) { g_loss = 0.0; g_done = 0; }
    } else {
        X = Bin; outh = g_Bh; outn = g_esq; scale = 65536.0f;
        r0 = (b - NA_BLK) * PROWS;
    }

    float* bufs[2] = {ptile, ptile + PROWS * PSTRIDE};

    auto fillc = [&](float* buf, int c) {
#pragma unroll
        for (int i = 0; i < 16; i++) {
            int idx = tid + i * 256;          // 0..4095
            int row = idx >> 4;               // 0..255
            int c4 = idx & 15;                // float4 slot in 64-col chunk
            const float* src = X + (size_t)(r0 + row) * DDIM + c + c4 * 4;
            CP16(smem_u32(buf + row * PSTRIDE + c4 * 4), src);
        }
        CP_COMMIT();
    };

    fillc(bufs[0], 0);
    float s = 0.f;
    for (int c = 0; c < DDIM; c += 64) {
        float* cur = bufs[(c >> 6) & 1];
        if (c + 64 < DDIM) {
            fillc(bufs[((c >> 6) & 1) ^ 1], c + 64);
            CP_WAIT(1);
        } else {
            CP_WAIT(0);
        }
        __syncthreads();
        // norm: own row, strictly sequential k order (bit-exact recipe)
        const float4* rowp = reinterpret_cast<const float4*>(cur + tid * PSTRIDE);
#pragma unroll
        for (int k4 = 0; k4 < 16; k4++) {
            float4 t = rowp[k4];
            s = __fadd_rn(s, __fmul_rn(t.x, t.x));
            s = __fadd_rn(s, __fmul_rn(t.y, t.y));
            s = __fadd_rn(s, __fmul_rn(t.z, t.z));
            s = __fadd_rn(s, __fmul_rn(t.w, t.w));
        }
        // convert: cooperative, coalesced global stores
#pragma unroll
        for (int i = 0; i < 16; i++) {
            int idx = tid + i * 256;
            int row = idx >> 4;
            int c4 = idx & 15;
            float4 t = *reinterpret_cast<const float4*>(cur + row * PSTRIDE + c4 * 4);
            __half2 h0 = __floats2half2_rn(t.x * scale, t.y * scale);
            __half2 h1 = __floats2half2_rn(t.z * scale, t.w * scale);
            uint2 pk;
            pk.x = *reinterpret_cast<unsigned*>(&h0);
            pk.y = *reinterpret_cast<unsigned*>(&h1);
            *reinterpret_cast<uint2*>(outh + (size_t)(r0 + row) * DDIM + c + c4 * 4) = pk;
        }
        __syncthreads();
    }
    outn[r0 + tid] = s;
}

// ---------------------------------------------------------------------------
// Pass 1 (R15 verbatim): fp16 HMMA GEMM, 128x256 tile, K=768 + score prune.
// ---------------------------------------------------------------------------
__global__ void __launch_bounds__(256, 2) pass1_kernel() {
    extern __shared__ char smem[];
    const uint32_t sb = smem_u32(smem);
    const uint32_t A_S[2] = {sb, sb + 16384};                 // 128 rows x 128B
    const uint32_t B_S[2] = {sb + 32768, sb + 32768 + 32768}; // 256 rows x 128B

    const int tid = threadIdx.x;
    const int wid = tid >> 5;
    const int lane = tid & 31;
    const int warp_m = wid >> 2;       // 0..1  (64 rows each)
    const int warp_n = wid & 3;        // 0..3  (64 cols each)
    const int bm = blockIdx.x * BM;
    const int bn = blockIdx.y * BN;

    uint32_t acc[4][8][2];             // half2-packed fp16 accumulators
#pragma unroll
    for (int i = 0; i < 4; i++)
#pragma unroll
        for (int j = 0; j < 8; j++) { acc[i][j][0] = 0u; acc[i][j][1] = 0u; }

    // hoisted fill addressing: 32-bit byte offsets; stage advance = +128B
    const char* Abase = reinterpret_cast<const char*>(g_Ah) +
                        (uint32_t)((bm + (tid >> 3)) * (DDIM * 2) + (tid & 7) * 16);
    const char* Bbase = reinterpret_cast<const char*>(g_Bh) +
                        (uint32_t)((bn + (tid >> 3)) * (DDIM * 2) + (tid & 7) * 16);
    const uint32_t dstsw = SW128((uint32_t)((tid >> 3) * 128 + (tid & 7) * 16));

    auto fill = [&](int stg, int s) {
        const char* ap = Abase + s * 128;
        const char* bp = Bbase + s * 128;
        const uint32_t da = A_S[stg] + dstsw;
        const uint32_t db = B_S[stg] + dstsw;
#pragma unroll
        for (int i = 0; i < 4; i++)
            CP16(da + i * 4096, ap + i * (32 * DDIM * 2));
#pragma unroll
        for (int i = 0; i < 8; i++)
            CP16(db + i * 4096, bp + i * (32 * DDIM * 2));
        CP_COMMIT();
    };

    fill(0, 0);
    fill(1, 1);

    const int a_r = warp_m * 64 + (lane & 7) + ((lane & 8) ? 8 : 0);  // + mi*16
    const int b_r = warp_n * 64 + (lane & 7) + ((lane & 8) ? 8 : 0);  // + bj*16
    const int chk = (lane >> 4) & 1;

    for (int s = 0; s < NSTAGE; s++) {
        if (s < NSTAGE - 1) { CP_WAIT(1); } else { CP_WAIT(0); }
        __syncthreads();
        const uint32_t Ab = A_S[s & 1], Bb = B_S[s & 1];
#pragma unroll
        for (int kk = 0; kk < 4; kk++) {
            const int ch = chk + kk * 2;
            uint32_t a[4][4];
#pragma unroll
            for (int mi = 0; mi < 4; mi++) {
                int r = a_r + mi * 16;
                ldm_x4(a[mi][0], a[mi][1], a[mi][2], a[mi][3],
                       Ab + (uint32_t)(r * 128 + ((ch * 16) ^ ((r & 7) << 4))));
            }
            uint32_t bf[4][4];
#pragma unroll
            for (int bj = 0; bj < 4; bj++) {
                int r = b_r + bj * 16;
                ldm_x4(bf[bj][0], bf[bj][1], bf[bj][2], bf[bj][3],
                       Bb + (uint32_t)(r * 128 + ((ch * 16) ^ ((r & 7) << 4))));
            }
#pragma unroll
            for (int mi = 0; mi < 4; mi++)
#pragma unroll
                for (int nj = 0; nj < 8; nj++)
                    mma_f16acc(acc[mi][nj], a[mi], bf[nj >> 1][nj & 1],
                               bf[nj >> 1][2 + (nj & 1)]);
        }
        __syncthreads();
        if (s + 2 < NSTAGE) fill(s & 1, s + 2);
    }

    // ---- epilogue: scores, running row-min, packed candidate collection ----
#pragma unroll
    for (int mi = 0; mi < 4; mi++) {
#pragma unroll
        for (int half = 0; half < 2; half++) {
            const int row = bm + warp_m * 64 + mi * 16 + (lane >> 2) + half * 8;
            float rmin = 3.4e38f;
            float sc[8][2];
#pragma unroll
            for (int nj = 0; nj < 8; nj++) {
                float2 d2 = __half22float2(
                    *reinterpret_cast<__half2*>(&acc[mi][nj][half]));
#pragma unroll
                for (int t = 0; t < 2; t++) {
                    int c = bn + warp_n * 64 + nj * 8 + (lane & 3) * 2 + t;
                    float dotp = t == 0 ? d2.x : d2.y;
                    float v = __fmaf_rn(MINUS2INV, dotp, g_esq[c]);
                    sc[nj][t] = v;
                    rmin = fminf(rmin, v);
                }
            }
            rmin = fminf(rmin, __shfl_xor_sync(0xFFFFFFFFu, rmin, 1));
            rmin = fminf(rmin, __shfl_xor_sync(0xFFFFFFFFu, rmin, 2));
            unsigned enc = fenc(rmin);
            unsigned old = 0xFFFFFFFFu;
            if ((lane & 3) == 0) old = atomicMin(&g_rowmin[row], enc);
            old = __shfl_sync(0xFFFFFFFFu, old, lane & ~3);
            float T = fdec(old < enc ? old : enc) + MARGIN;
#pragma unroll
            for (int nj = 0; nj < 8; nj++)
#pragma unroll
                for (int t = 0; t < 2; t++) {
                    if (sc[nj][t] <= T) {
                        int c = bn + warp_n * 64 + nj * 8 + (lane & 3) * 2 + t;
                        int pos = atomicAdd(&g_cnt[row], 1);
                        if (pos < CAP)
                            g_cand[(size_t)row * CAP + pos] =
                                ((unsigned long long)fenc(sc[nj][t]) << 32) |
                                (unsigned long long)(unsigned)c;
                    }
                }
        }
    }
}

// ---------------------------------------------------------------------------
// Rerank: one WARP per row (R15 verbatim).
// ---------------------------------------------------------------------------
__global__ void __launch_bounds__(256) rerank_kernel(const float* __restrict__ A,
                                                     const float* __restrict__ B) {
    const int n = blockIdx.x * 8 + (threadIdx.x >> 5);
    const int lane = threadIdx.x & 31;

    const float zq = g_zsq[n];
    const float thr = fdec(g_rowmin[n]) + FILTER;
    const float* z = A + (size_t)n * DDIM;
    int cnt = g_cnt[n];
    if (cnt > CAP) cnt = CAP;

    unsigned long long best = ~0ULL;
    for (int i = lane; i < cnt; i += 32) {
        unsigned long long key = g_cand[(size_t)n * CAP + i];
        float sc = fdec((unsigned)(key >> 32));
        if (sc > thr) continue;
        int c = (int)(key & 0xFFFFFFFFULL);
        const float4* e4 = reinterpret_cast<const float4*>(B + (size_t)c * DDIM);
        const float4* z4 = reinterpret_cast<const float4*>(z);
        float dot = 0.f;
#pragma unroll 4
        for (int k = 0; k < DDIM / 4; k++) {
            float4 ev = __ldg(&e4[k]);
            float4 zv = __ldg(&z4[k]);
            dot = __fmaf_rn(zv.x, ev.x, dot);
            dot = __fmaf_rn(zv.y, ev.y, dot);
            dot = __fmaf_rn(zv.z, ev.z, dot);
            dot = __fmaf_rn(zv.w, ev.w, dot);
        }
        float anchor = __fadd_rn(zq, g_esq[c]);               // fl(z2 + e2)
        float dist = __fsub_rn(anchor, __fadd_rn(dot, dot));  // fl(a - 2*dot)
        unsigned long long k2 =
            ((unsigned long long)__float_as_uint(dist) << 32) |
            (unsigned long long)(unsigned)c;
        best = k2 < best ? k2 : best;
    }
#pragma unroll
    for (int o = 16; o > 0; o >>= 1) {
        unsigned long long other = __shfl_xor_sync(0xFFFFFFFFu, best, o);
        best = other < best ? other : best;
    }
    if (lane == 0) g_code[n] = (int)(best & 0xFFFFFFFFULL);
}

// ---------------------------------------------------------------------------
// STE + loss (R15 verbatim): block per row, float4 streams, last-block loss.
// ---------------------------------------------------------------------------
__global__ void __launch_bounds__(256) ste_kernel(const float* __restrict__ A,
                                                  const float* __restrict__ B,
                                                  float* __restrict__ out_codes,
                                                  float* __restrict__ out_q,
                                                  float* __restrict__ out_loss,
                                                  double inv_nd) {
    const int n = blockIdx.x;
    const int tid = threadIdx.x;
    const int code = g_code[n];
    if (tid == 0) out_codes[n] = (float)code;

    const float4* z4 = reinterpret_cast<const float4*>(A + (size_t)n * DDIM);
    const float4* q4 = reinterpret_cast<const float4*>(B + (size_t)code * DDIM);
    float4* o4 = reinterpret_cast<float4*>(out_q + (size_t)n * DDIM);

    float ls = 0.f;
    if (tid < DDIM / 4) {                      // 192 active threads
        float4 zv = __ldg(&z4[tid]);
        float4 qv = __ldg(&q4[tid]);
        float4 ov;
        ov.x = __fadd_rn(zv.x, __fsub_rn(qv.x, zv.x));
        ov.y = __fadd_rn(zv.y, __fsub_rn(qv.y, zv.y));
        ov.z = __fadd_rn(zv.z, __fsub_rn(qv.z, zv.z));
        ov.w = __fadd_rn(zv.w, __fsub_rn(qv.w, zv.w));
        o4[tid] = ov;
        float dx = zv.x - qv.x, dy = zv.y - qv.y;
        float dz = zv.z - qv.z, dw = zv.w - qv.w;
        ls = __fmaf_rn(dx, dx, __fmaf_rn(dy, dy,
             __fmaf_rn(dz, dz, __fmul_rn(dw, dw))));
    }
#pragma unroll
    for (int o = 16; o > 0; o >>= 1) ls += __shfl_xor_sync(0xFFFFFFFFu, ls, o);
    __shared__ float wsum[8];
    int w = tid >> 5;
    if ((tid & 31) == 0) wsum[w] = ls;
    __syncthreads();
    if (tid == 0) {
        float s = 0.f;
        for (int k = 0; k < 8; k++) s += wsum[k];
        atomicAdd(&g_loss, (double)s);
        __threadfence();
        int d = atomicAdd(&g_done, 1);
        if (d == (int)gridDim.x - 1) {
            __threadfence();
            out_loss[0] = (float)(g_loss * inv_nd * 1.25);
        }
    }
}

// ---------------------------------------------------------------------------
extern "C" void kernel_launch(void* const* d_in, const int* in_sizes, int n_in,
                              void* d_out, int out_size) {
    const float* A = (const float*)d_in[0];  // embeddings (4096 x 768)
    const float* B = (const float*)d_in[1];  // codebook  (65536 x 768)
    const int N = in_sizes[0] / DDIM;
    const int K = in_sizes[1] / DDIM;

    float* out = (float*)d_out;
    float* out_codes = out;
    float* out_q = out + N;
    float* out_loss = out + N + (size_t)N * DDIM;

    static const int SMEM_BYTES = 2 * 16384 + 2 * 32768;  // 96 KB
    cudaFuncSetAttribute(pass1_kernel, cudaFuncAttributeMaxDynamicSharedMemorySize,
                         SMEM_BYTES);
    cudaFuncSetAttribute(prep_kernel, cudaFuncAttributeMaxDynamicSharedMemorySize,
                         PREP_SMEM);

    // prep v3: init + A + B, all-thread norm chains, cp.async pipelined
    prep_kernel<<<(N + K) / PROWS, 256, PREP_SMEM>>>(A, B);

    dim3 grid(N / BM, K / BN);   // (32, 256) — m fastest for B-strip L2 reuse
    pass1_kernel<<<grid, 256, SMEM_BYTES>>>(
    );

    rerank_kernel<<<N / 8, 256>>>(A, B);
    ste_kernel<<<N, 256>>>(A, B, out_codes, out_q, out_loss,
                           1.0 / ((double)N * (double)DDIM));
}